// round 1
// baseline (speedup 1.0000x reference)
#include <cuda_runtime.h>
#include <cuda_bf16.h>

// Problem constants:
//   input   [64, 32, 32, 16, 16] f32   (B, CLN, QL, IH, IW)
//   context [64, 256, 128]       f32   (B, CDF, SL)
//   W       [8192, 256]          f32   (IDF, CDF)
// Outputs (concatenated in d_out):
//   wc    [64, 32, 32, 16, 16] f32  -> 16,777,216 elems
//   attnT [64, 128, 32]        f32  ->    262,144 elems

#define B_SZ   64
#define QL_SZ  32
#define CDF_SZ 256
#define SL_SZ  128
#define IDF_SZ 8192
#define WC_ELEMS (B_SZ * IDF_SZ * QL_SZ)   // 16777216

// Scratch (device globals; no allocation allowed)
__device__ float g_T2[B_SZ * QL_SZ * CDF_SZ];   // [b][q][c]   2 MB
__device__ float g_CA[B_SZ * CDF_SZ * QL_SZ];   // [b][c][q]   2 MB

// ---------- packed f32x2 helpers (sm_103a) ----------
__device__ __forceinline__ unsigned long long ffma2(unsigned long long a,
                                                    unsigned long long b,
                                                    unsigned long long c) {
    unsigned long long d;
    asm("fma.rn.f32x2 %0, %1, %2, %3;" : "=l"(d) : "l"(a), "l"(b), "l"(c));
    return d;
}
__device__ __forceinline__ float2 unpk(unsigned long long v) {
    float2 f;
    asm("mov.b64 {%0, %1}, %2;" : "=f"(f.x), "=f"(f.y) : "l"(v));
    return f;
}

// ============================================================================
// Kernel 1: T2[b][q][c] = sum_d targetT[b][q][d] * W[d][c]
//   targetT[b][q][d] = input[b][d>>8][q][d&255]  (d = cl*256 + hw)
//   Per block: b fixed, 64-wide c-tile.  M=32(q), N=64(c), K=8192(d).
//   A-operand duplicated into pairs in smem so FFMA2 needs no packing MOVs.
// ============================================================================
#define RSA 68   // As2 row stride (pairs for 32 m = 64 floats) + pad, 16B-aligned rows

__global__ __launch_bounds__(128) void k1_gemm_T2(const float* __restrict__ inp,
                                                  const float* __restrict__ W) {
    __shared__ float As2[32 * RSA];   // [kk][2m] duplicated A values
    __shared__ float Bs[32 * 64];     // [kk][n]
    const int b   = blockIdx.y;
    const int n0  = blockIdx.x * 64;
    const int tid = threadIdx.x;
    const int r   = tid >> 4;   // 0..7  -> rows 4r..4r+3
    const int cL  = tid & 15;   // 0..15 -> cols 4cL..4cL+3

    unsigned long long acc[4][2];
#pragma unroll
    for (int i = 0; i < 4; ++i) { acc[i][0] = 0ULL; acc[i][1] = 0ULL; }

    for (int k0 = 0; k0 < IDF_SZ; k0 += 32) {
        const int cl  = k0 >> 8;
        const int hw0 = k0 & 255;
        // load A 32(m) x 32(k), transpose + duplicate into As2[kk][2m]
#pragma unroll
        for (int i = 0; i < 2; ++i) {
            int idx = tid + i * 128;          // 0..255
            int m = idx >> 3, v = idx & 7;
            float4 a = *(const float4*)(inp + ((b * 32 + cl) * 32 + m) * 256 + hw0 + 4 * v);
            float* d0 = As2 + (4 * v) * RSA + 2 * m;
            d0[0]         = a.x; d0[1]         = a.x;
            d0[RSA]       = a.y; d0[RSA + 1]   = a.y;
            d0[2 * RSA]   = a.z; d0[2 * RSA+1] = a.z;
            d0[3 * RSA]   = a.w; d0[3 * RSA+1] = a.w;
        }
        // load B 32(k) x 64(n)
#pragma unroll
        for (int i = 0; i < 4; ++i) {
            int idx = tid + i * 128;          // 0..511
            int kk = idx >> 4, v = idx & 15;
            *(float4*)(Bs + kk * 64 + 4 * v) =
                *(const float4*)(W + (k0 + kk) * 256 + n0 + 4 * v);
        }
        __syncthreads();
#pragma unroll
        for (int kk = 0; kk < 32; ++kk) {
            ulonglong2 A01 = *(const ulonglong2*)(As2 + kk * RSA + 8 * r);
            ulonglong2 A23 = *(const ulonglong2*)(As2 + kk * RSA + 8 * r + 4);
            ulonglong2 Bp  = *(const ulonglong2*)(Bs + kk * 64 + 4 * cL);
            acc[0][0] = ffma2(A01.x, Bp.x, acc[0][0]);
            acc[0][1] = ffma2(A01.x, Bp.y, acc[0][1]);
            acc[1][0] = ffma2(A01.y, Bp.x, acc[1][0]);
            acc[1][1] = ffma2(A01.y, Bp.y, acc[1][1]);
            acc[2][0] = ffma2(A23.x, Bp.x, acc[2][0]);
            acc[2][1] = ffma2(A23.x, Bp.y, acc[2][1]);
            acc[3][0] = ffma2(A23.y, Bp.x, acc[3][0]);
            acc[3][1] = ffma2(A23.y, Bp.y, acc[3][1]);
        }
        __syncthreads();
    }
#pragma unroll
    for (int i = 0; i < 4; ++i) {
        int m = 4 * r + i;
        float2 p0 = unpk(acc[i][0]);
        float2 p1 = unpk(acc[i][1]);
        *(float4*)(g_T2 + (b * 32 + m) * 256 + n0 + 4 * cL) =
            make_float4(p0.x, p0.y, p1.x, p1.y);
    }
}

// ============================================================================
// Kernel 2 (one block per b, 256 threads):
//   attn[q][s] = sum_c T2[b][q][c] * ctx[b][c][s]  -> softmax over s
//   write attnT[b][s][q] ; ctx_attn[b][c][q] = sum_s ctx[b][c][s]*attn[q][s]
// ============================================================================
#define APAD 133   // attn row stride (q*133+s) -> conflict-free transposed access

__global__ __launch_bounds__(256) void k2_attn(const float* __restrict__ ctx,
                                               float* __restrict__ outAttnT) {
    extern __shared__ float s2[];
    float* T2s  = s2;           // 8192 floats  [q][c]
    float* attn = s2 + 8192;    // 32*APAD floats

    const int b   = blockIdx.x;
    const int tid = threadIdx.x;

#pragma unroll
    for (int i = 0; i < 8; ++i) {
        int idx = tid + i * 256;   // 0..2047 float4s
        *(float4*)(T2s + 4 * idx) = *(const float4*)(g_T2 + b * 8192 + 4 * idx);
    }
    __syncthreads();

    // logits
    {
        const int s     = tid & 127;
        const int qbase = (tid >> 7) * 16;
        float acc[16];
#pragma unroll
        for (int j = 0; j < 16; ++j) acc[j] = 0.0f;
        const float* cb = ctx + (b * 256) * 128 + s;
        for (int c = 0; c < 256; ++c) {
            float cv = cb[c * 128];
#pragma unroll
            for (int j = 0; j < 16; ++j)
                acc[j] += T2s[(qbase + j) * 256 + c] * cv;
        }
#pragma unroll
        for (int j = 0; j < 16; ++j) attn[(qbase + j) * APAD + s] = acc[j];
    }
    __syncthreads();

    // softmax over s (128) per q row; 8 warps x 4 rows
    {
        const int warp = tid >> 5, lane = tid & 31;
        for (int qi = 0; qi < 4; ++qi) {
            int q = warp * 4 + qi;
            float v0 = attn[q * APAD + lane];
            float v1 = attn[q * APAD + lane + 32];
            float v2 = attn[q * APAD + lane + 64];
            float v3 = attn[q * APAD + lane + 96];
            float mx = fmaxf(fmaxf(v0, v1), fmaxf(v2, v3));
#pragma unroll
            for (int o = 16; o > 0; o >>= 1)
                mx = fmaxf(mx, __shfl_xor_sync(0xffffffffu, mx, o));
            float e0 = expf(v0 - mx), e1 = expf(v1 - mx);
            float e2 = expf(v2 - mx), e3 = expf(v3 - mx);
            float sm = e0 + e1 + e2 + e3;
#pragma unroll
            for (int o = 16; o > 0; o >>= 1)
                sm += __shfl_xor_sync(0xffffffffu, sm, o);
            float inv = 1.0f / sm;
            attn[q * APAD + lane]      = e0 * inv;
            attn[q * APAD + lane + 32] = e1 * inv;
            attn[q * APAD + lane + 64] = e2 * inv;
            attn[q * APAD + lane + 96] = e3 * inv;
        }
    }
    __syncthreads();

    // attnT output: [b][s][q]
#pragma unroll
    for (int i = 0; i < 16; ++i) {
        int idx = tid + i * 256;          // 0..4095
        int ss = idx >> 5, q = idx & 31;
        outAttnT[b * 4096 + idx] = attn[q * APAD + ss];
    }

    // ctx_attn[b][c][q]
    {
        const int c = tid;                // 0..255
        float a2[32];
#pragma unroll
        for (int j = 0; j < 32; ++j) a2[j] = 0.0f;
        const float* cb = ctx + (b * 256 + c) * 128;
        for (int s = 0; s < 128; ++s) {
            float cv = cb[s];
#pragma unroll
            for (int q = 0; q < 32; ++q)
                a2[q] += attn[q * APAD + s] * cv;
        }
        float* dst = g_CA + (b * 256 + c) * 32;
#pragma unroll
        for (int j = 0; j < 8; ++j)
            *(float4*)(dst + 4 * j) =
                make_float4(a2[4*j], a2[4*j+1], a2[4*j+2], a2[4*j+3]);
    }
}

// ============================================================================
// Kernel 3: wc[b][d][q] = sum_c W[d][c] * ctx_attn[b][c][q], then write with
// the torch-.view scramble:  out[b][c2][q2][hw],
//   c2=(d>>3)&31, q2=d>>8, hw=(d&7)*32+q
//   Per block: b fixed, 128-row d-tile.  M=128(d), N=32(q), K=256(c).
// ============================================================================
#define RSW 260   // Ws2 row stride (pairs for 128 m = 256 floats) + pad

__global__ __launch_bounds__(128) void k3_gemm_out(const float* __restrict__ W,
                                                   float* __restrict__ out0) {
    extern __shared__ float s3[];
    float* Cs  = s3;           // 256*32 floats [c][q]
    float* Ws2 = s3 + 8192;    // 32*RSW floats [kk][2m] duplicated

    const int b   = blockIdx.y;
    const int m0  = blockIdx.x * 128;
    const int tid = threadIdx.x;
    const int mr  = tid >> 2;        // 0..31 -> rows 4mr..4mr+3
    const int q0  = (tid & 3) * 8;   // 0,8,16,24

#pragma unroll
    for (int i = 0; i < 16; ++i) {
        int idx = tid + i * 128;     // 0..2047 float4s
        *(float4*)(Cs + 4 * idx) = *(const float4*)(g_CA + b * 8192 + 4 * idx);
    }

    unsigned long long acc[4][4];
#pragma unroll
    for (int i = 0; i < 4; ++i)
#pragma unroll
        for (int p = 0; p < 4; ++p) acc[i][p] = 0ULL;

    for (int k0 = 0; k0 < 256; k0 += 32) {
        __syncthreads();   // first iter: Cs visible; later: Ws2 readers done
#pragma unroll
        for (int i = 0; i < 8; ++i) {
            int idx = tid + i * 128;  // 0..1023
            int m = idx >> 3, v = idx & 7;
            float4 wv = *(const float4*)(W + (m0 + m) * 256 + k0 + 4 * v);
            float* d0 = Ws2 + (4 * v) * RSW + 2 * m;
            d0[0]         = wv.x; d0[1]         = wv.x;
            d0[RSW]       = wv.y; d0[RSW + 1]   = wv.y;
            d0[2 * RSW]   = wv.z; d0[2 * RSW+1] = wv.z;
            d0[3 * RSW]   = wv.w; d0[3 * RSW+1] = wv.w;
        }
        __syncthreads();
#pragma unroll
        for (int kk = 0; kk < 32; ++kk) {
            int c = k0 + kk;
            ulonglong2 W01 = *(const ulonglong2*)(Ws2 + kk * RSW + 8 * mr);
            ulonglong2 W23 = *(const ulonglong2*)(Ws2 + kk * RSW + 8 * mr + 4);
            ulonglong2 C0  = *(const ulonglong2*)(Cs + c * 32 + q0);
            ulonglong2 C1  = *(const ulonglong2*)(Cs + c * 32 + q0 + 4);
            acc[0][0] = ffma2(W01.x, C0.x, acc[0][0]);
            acc[0][1] = ffma2(W01.x, C0.y, acc[0][1]);
            acc[0][2] = ffma2(W01.x, C1.x, acc[0][2]);
            acc[0][3] = ffma2(W01.x, C1.y, acc[0][3]);
            acc[1][0] = ffma2(W01.y, C0.x, acc[1][0]);
            acc[1][1] = ffma2(W01.y, C0.y, acc[1][1]);
            acc[1][2] = ffma2(W01.y, C1.x, acc[1][2]);
            acc[1][3] = ffma2(W01.y, C1.y, acc[1][3]);
            acc[2][0] = ffma2(W23.x, C0.x, acc[2][0]);
            acc[2][1] = ffma2(W23.x, C0.y, acc[2][1]);
            acc[2][2] = ffma2(W23.x, C1.x, acc[2][2]);
            acc[2][3] = ffma2(W23.x, C1.y, acc[2][3]);
            acc[3][0] = ffma2(W23.y, C0.x, acc[3][0]);
            acc[3][1] = ffma2(W23.y, C0.y, acc[3][1]);
            acc[3][2] = ffma2(W23.y, C1.x, acc[3][2]);
            acc[3][3] = ffma2(W23.y, C1.y, acc[3][3]);
        }
    }

#pragma unroll
    for (int i = 0; i < 4; ++i) {
        int d  = m0 + 4 * mr + i;
        int c2 = (d >> 3) & 31;
        int q2 = d >> 8;
        int base = ((b * 32 + c2) * 32 + q2) * 256 + (d & 7) * 32 + q0;
        float2 p0 = unpk(acc[i][0]), p1 = unpk(acc[i][1]);
        float2 p2 = unpk(acc[i][2]), p3 = unpk(acc[i][3]);
        *(float4*)(out0 + base)     = make_float4(p0.x, p0.y, p1.x, p1.y);
        *(float4*)(out0 + base + 4) = make_float4(p2.x, p2.y, p3.x, p3.y);
    }
}

// ============================================================================
extern "C" void kernel_launch(void* const* d_in, const int* in_sizes, int n_in,
                              void* d_out, int out_size) {
    const float* inp = (const float*)d_in[0];   // input
    const float* ctx = (const float*)d_in[1];   // context
    const float* W   = (const float*)d_in[2];   // W [8192,256]
    float* out = (float*)d_out;

    const int SMEM2 = (8192 + 32 * APAD) * 4;   // 49,792 B
    const int SMEM3 = (8192 + 32 * RSW) * 4;    // 66,048 B
    cudaFuncSetAttribute(k2_attn, cudaFuncAttributeMaxDynamicSharedMemorySize, SMEM2);
    cudaFuncSetAttribute(k3_gemm_out, cudaFuncAttributeMaxDynamicSharedMemorySize, SMEM3);

    k1_gemm_T2<<<dim3(4, B_SZ), 128>>>(inp, W);
    k2_attn<<<B_SZ, 256, SMEM2>>>(ctx, out + WC_ELEMS);
    k3_gemm_out<<<dim3(64, B_SZ), 128, SMEM3>>>(W, out);
}

// round 2
// speedup vs baseline: 1.3554x; 1.3554x over previous
#include <cuda_runtime.h>
#include <cuda_bf16.h>

// Problem constants:
//   input   [64, 32, 32, 16, 16] f32   (B, CLN, QL, IH, IW)
//   context [64, 256, 128]       f32   (B, CDF, SL)
//   W       [8192, 256]          f32   (IDF, CDF)
// Outputs (concatenated in d_out):
//   wc    [64, 32, 32, 16, 16] f32  -> 16,777,216 elems
//   attnT [64, 128, 32]        f32  ->    262,144 elems

#define B_SZ   64
#define QL_SZ  32
#define CDF_SZ 256
#define SL_SZ  128
#define IDF_SZ 8192
#define WC_ELEMS (B_SZ * IDF_SZ * QL_SZ)   // 16777216
#define KSPLIT 8
#define T2_STRIDE (B_SZ * QL_SZ * CDF_SZ)  // 524288 floats per k-split partial

// Scratch (device globals; no allocation allowed)
__device__ float g_T2p[KSPLIT * T2_STRIDE];     // [ks][b][q][c]  16 MB
__device__ float g_CA[B_SZ * CDF_SZ * QL_SZ];   // [b][c][q]       2 MB

// ---------- packed f32x2 helpers (sm_103a) ----------
__device__ __forceinline__ unsigned long long ffma2(unsigned long long a,
                                                    unsigned long long b,
                                                    unsigned long long c) {
    unsigned long long d;
    asm("fma.rn.f32x2 %0, %1, %2, %3;" : "=l"(d) : "l"(a), "l"(b), "l"(c));
    return d;
}
__device__ __forceinline__ float2 unpk(unsigned long long v) {
    float2 f;
    asm("mov.b64 {%0, %1}, %2;" : "=f"(f.x), "=f"(f.y) : "l"(v));
    return f;
}

// ============================================================================
// Kernel 1: T2[b][q][c] = sum_d targetT[b][q][d] * W[d][c]
//   targetT[b][q][d] = input[b][d>>8][q][d&255]
//   k-split x8: each block does K range [ks*1024, ks*1024+1024), writes a
//   partial into g_T2p[ks].  Grid: (4 n-tiles x 8 ksplit, 64 b) = 2048 blocks.
// ============================================================================
#define RSA 68   // As2 row stride (pairs for 32 m = 64 floats) + pad

__global__ __launch_bounds__(128) void k1_gemm_T2(const float* __restrict__ inp,
                                                  const float* __restrict__ W) {
    __shared__ float As2[32 * RSA];   // [kk][2m] duplicated A values
    __shared__ float Bs[32 * 64];     // [kk][n]
    const int b   = blockIdx.y;
    const int n0  = (blockIdx.x & 3) * 64;
    const int ks  = blockIdx.x >> 2;
    const int tid = threadIdx.x;
    const int r   = tid >> 4;   // 0..7  -> rows 4r..4r+3
    const int cL  = tid & 15;   // 0..15 -> cols 4cL..4cL+3

    unsigned long long acc[4][2];
#pragma unroll
    for (int i = 0; i < 4; ++i) { acc[i][0] = 0ULL; acc[i][1] = 0ULL; }

    const int kbeg = ks * (IDF_SZ / KSPLIT);
    const int kend = kbeg + (IDF_SZ / KSPLIT);
    for (int k0 = kbeg; k0 < kend; k0 += 32) {
        const int cl  = k0 >> 8;
        const int hw0 = k0 & 255;
        // load A 32(m) x 32(k), transpose + duplicate into As2[kk][2m]
#pragma unroll
        for (int i = 0; i < 2; ++i) {
            int idx = tid + i * 128;          // 0..255
            int m = idx >> 3, v = idx & 7;
            float4 a = *(const float4*)(inp + ((b * 32 + cl) * 32 + m) * 256 + hw0 + 4 * v);
            float* d0 = As2 + (4 * v) * RSA + 2 * m;
            d0[0]         = a.x; d0[1]         = a.x;
            d0[RSA]       = a.y; d0[RSA + 1]   = a.y;
            d0[2 * RSA]   = a.z; d0[2 * RSA+1] = a.z;
            d0[3 * RSA]   = a.w; d0[3 * RSA+1] = a.w;
        }
        // load B 32(k) x 64(n)
#pragma unroll
        for (int i = 0; i < 4; ++i) {
            int idx = tid + i * 128;          // 0..511
            int kk = idx >> 4, v = idx & 15;
            *(float4*)(Bs + kk * 64 + 4 * v) =
                *(const float4*)(W + (k0 + kk) * 256 + n0 + 4 * v);
        }
        __syncthreads();
#pragma unroll
        for (int kk = 0; kk < 32; ++kk) {
            ulonglong2 A01 = *(const ulonglong2*)(As2 + kk * RSA + 8 * r);
            ulonglong2 A23 = *(const ulonglong2*)(As2 + kk * RSA + 8 * r + 4);
            ulonglong2 Bp  = *(const ulonglong2*)(Bs + kk * 64 + 4 * cL);
            acc[0][0] = ffma2(A01.x, Bp.x, acc[0][0]);
            acc[0][1] = ffma2(A01.x, Bp.y, acc[0][1]);
            acc[1][0] = ffma2(A01.y, Bp.x, acc[1][0]);
            acc[1][1] = ffma2(A01.y, Bp.y, acc[1][1]);
            acc[2][0] = ffma2(A23.x, Bp.x, acc[2][0]);
            acc[2][1] = ffma2(A23.x, Bp.y, acc[2][1]);
            acc[3][0] = ffma2(A23.y, Bp.x, acc[3][0]);
            acc[3][1] = ffma2(A23.y, Bp.y, acc[3][1]);
        }
        __syncthreads();
    }
    float* dst = g_T2p + (size_t)ks * T2_STRIDE + b * 8192;
#pragma unroll
    for (int i = 0; i < 4; ++i) {
        int m = 4 * r + i;
        float2 p0 = unpk(acc[i][0]);
        float2 p1 = unpk(acc[i][1]);
        *(float4*)(dst + m * 256 + n0 + 4 * cL) =
            make_float4(p0.x, p0.y, p1.x, p1.y);
    }
}

// ============================================================================
// Kernel 2 (4 blocks per b, each handles 8 q-rows; 256 threads):
//   reduce T2 partials, logits, softmax, write attnT[b][s][q], ctx_attn.
// ============================================================================
#define APAD 133

__global__ __launch_bounds__(256) void k2_attn(const float* __restrict__ ctx,
                                               float* __restrict__ outAttnT) {
    __shared__ float T2s[8 * 256];     // [qlocal][c]
    __shared__ float attn[8 * APAD];   // [qlocal][s]

    const int b   = blockIdx.x >> 2;
    const int q0  = (blockIdx.x & 3) * 8;
    const int tid = threadIdx.x;

    // reduce 8 k-split partials for our 8 q rows (2048 floats = 512 float4)
#pragma unroll
    for (int i = 0; i < 2; ++i) {
        int idx = tid + i * 256;               // 0..511
        int ql  = idx >> 6;                    // 64 float4 per q row
        int cc  = (idx & 63) * 4;
        const float* src = g_T2p + (b * 32 + q0 + ql) * 256 + cc;
        float4 s = *(const float4*)(src);
#pragma unroll
        for (int p = 1; p < KSPLIT; ++p) {
            float4 t = *(const float4*)(src + (size_t)p * T2_STRIDE);
            s.x += t.x; s.y += t.y; s.z += t.z; s.w += t.w;
        }
        *(float4*)(T2s + 4 * idx) = s;
    }
    __syncthreads();

    // logits: attn[ql][s] = sum_c T2s[ql][c] * ctx[b][c][s]
    {
        const int s = tid & 127;
        const int g = tid >> 7;        // 0/1 -> ql 4g..4g+3
        float acc[4] = {0.f, 0.f, 0.f, 0.f};
        const float* cb = ctx + b * 256 * 128 + s;
        const float* t2 = T2s + g * 4 * 256;
        for (int c = 0; c < 256; ++c) {
            float cv = cb[c * 128];
#pragma unroll
            for (int j = 0; j < 4; ++j)
                acc[j] += t2[j * 256 + c] * cv;
        }
#pragma unroll
        for (int j = 0; j < 4; ++j) attn[(g * 4 + j) * APAD + s] = acc[j];
    }
    __syncthreads();

    // softmax over s (128) per row; 8 warps, one row each
    {
        const int warp = tid >> 5, lane = tid & 31;
        float v0 = attn[warp * APAD + lane];
        float v1 = attn[warp * APAD + lane + 32];
        float v2 = attn[warp * APAD + lane + 64];
        float v3 = attn[warp * APAD + lane + 96];
        float mx = fmaxf(fmaxf(v0, v1), fmaxf(v2, v3));
#pragma unroll
        for (int o = 16; o > 0; o >>= 1)
            mx = fmaxf(mx, __shfl_xor_sync(0xffffffffu, mx, o));
        float e0 = expf(v0 - mx), e1 = expf(v1 - mx);
        float e2 = expf(v2 - mx), e3 = expf(v3 - mx);
        float sm = e0 + e1 + e2 + e3;
#pragma unroll
        for (int o = 16; o > 0; o >>= 1)
            sm += __shfl_xor_sync(0xffffffffu, sm, o);
        float inv = 1.0f / sm;
        attn[warp * APAD + lane]      = e0 * inv;
        attn[warp * APAD + lane + 32] = e1 * inv;
        attn[warp * APAD + lane + 64] = e2 * inv;
        attn[warp * APAD + lane + 96] = e3 * inv;
    }
    __syncthreads();

    // attnT output: [b][s][q0+ql]
#pragma unroll
    for (int i = 0; i < 4; ++i) {
        int idx = tid + i * 256;           // 0..1023
        int s = idx >> 3, ql = idx & 7;
        outAttnT[b * 4096 + s * 32 + q0 + ql] = attn[ql * APAD + s];
    }

    // ctx_attn[b][c][q0..q0+7] = sum_s ctx[b][c][s] * attn[ql][s]
    {
        const int c = tid;                 // 0..255
        float a2[8] = {0.f,0.f,0.f,0.f,0.f,0.f,0.f,0.f};
        const float* cb = ctx + (b * 256 + c) * 128;
        for (int s = 0; s < 128; ++s) {
            float cv = cb[s];
#pragma unroll
            for (int j = 0; j < 8; ++j)
                a2[j] += attn[j * APAD + s] * cv;
        }
        float* dst = g_CA + (b * 256 + c) * 32 + q0;
        *(float4*)(dst)     = make_float4(a2[0], a2[1], a2[2], a2[3]);
        *(float4*)(dst + 4) = make_float4(a2[4], a2[5], a2[6], a2[7]);
    }
}

// ============================================================================
// Kernel 3: wc[b][d][q] = sum_c W[d][c] * ctx_attn[b][c][q], torch-.view write
//   out[b][c2][q2][hw]: c2=(d>>3)&31, q2=d>>8, hw=(d&7)*32+q
//   M=128(d), N=32(q), K=256(c); W staged 16 k at a time (smem 49 KB).
// ============================================================================
#define RSW 260   // Ws2 row stride (pairs for 128 m = 256 floats) + pad

__global__ __launch_bounds__(128) void k3_gemm_out(const float* __restrict__ W,
                                                   float* __restrict__ out0) {
    extern __shared__ float s3[];
    float* Cs  = s3;            // 256*32 floats [c][q]
    float* Ws2 = s3 + 8192;     // 16*RSW floats [kk][2m] duplicated

    const int b   = blockIdx.y;
    const int m0  = blockIdx.x * 128;
    const int tid = threadIdx.x;
    const int mr  = tid >> 2;        // 0..31 -> rows 4mr..4mr+3
    const int q0  = (tid & 3) * 8;   // 0,8,16,24

#pragma unroll
    for (int i = 0; i < 16; ++i) {
        int idx = tid + i * 128;     // 0..2047 float4s
        *(float4*)(Cs + 4 * idx) = *(const float4*)(g_CA + b * 8192 + 4 * idx);
    }

    unsigned long long acc[4][4];
#pragma unroll
    for (int i = 0; i < 4; ++i)
#pragma unroll
        for (int p = 0; p < 4; ++p) acc[i][p] = 0ULL;

    for (int k0 = 0; k0 < 256; k0 += 16) {
        __syncthreads();   // first iter: Cs visible; later: Ws2 readers done
#pragma unroll
        for (int i = 0; i < 4; ++i) {
            int idx = tid + i * 128;  // 0..511
            int m = idx >> 2, v = idx & 3;
            float4 wv = *(const float4*)(W + (m0 + m) * 256 + k0 + 4 * v);
            float* d0 = Ws2 + (4 * v) * RSW + 2 * m;
            d0[0]         = wv.x; d0[1]         = wv.x;
            d0[RSW]       = wv.y; d0[RSW + 1]   = wv.y;
            d0[2 * RSW]   = wv.z; d0[2 * RSW+1] = wv.z;
            d0[3 * RSW]   = wv.w; d0[3 * RSW+1] = wv.w;
        }
        __syncthreads();
#pragma unroll
        for (int kk = 0; kk < 16; ++kk) {
            int c = k0 + kk;
            ulonglong2 W01 = *(const ulonglong2*)(Ws2 + kk * RSW + 8 * mr);
            ulonglong2 W23 = *(const ulonglong2*)(Ws2 + kk * RSW + 8 * mr + 4);
            ulonglong2 C0  = *(const ulonglong2*)(Cs + c * 32 + q0);
            ulonglong2 C1  = *(const ulonglong2*)(Cs + c * 32 + q0 + 4);
            acc[0][0] = ffma2(W01.x, C0.x, acc[0][0]);
            acc[0][1] = ffma2(W01.x, C0.y, acc[0][1]);
            acc[0][2] = ffma2(W01.x, C1.x, acc[0][2]);
            acc[0][3] = ffma2(W01.x, C1.y, acc[0][3]);
            acc[1][0] = ffma2(W01.y, C0.x, acc[1][0]);
            acc[1][1] = ffma2(W01.y, C0.y, acc[1][1]);
            acc[1][2] = ffma2(W01.y, C1.x, acc[1][2]);
            acc[1][3] = ffma2(W01.y, C1.y, acc[1][3]);
            acc[2][0] = ffma2(W23.x, C0.x, acc[2][0]);
            acc[2][1] = ffma2(W23.x, C0.y, acc[2][1]);
            acc[2][2] = ffma2(W23.x, C1.x, acc[2][2]);
            acc[2][3] = ffma2(W23.x, C1.y, acc[2][3]);
            acc[3][0] = ffma2(W23.y, C0.x, acc[3][0]);
            acc[3][1] = ffma2(W23.y, C0.y, acc[3][1]);
            acc[3][2] = ffma2(W23.y, C1.x, acc[3][2]);
            acc[3][3] = ffma2(W23.y, C1.y, acc[3][3]);
        }
    }

#pragma unroll
    for (int i = 0; i < 4; ++i) {
        int d  = m0 + 4 * mr + i;
        int c2 = (d >> 3) & 31;
        int q2 = d >> 8;
        int base = ((b * 32 + c2) * 32 + q2) * 256 + (d & 7) * 32 + q0;
        float2 p0 = unpk(acc[i][0]), p1 = unpk(acc[i][1]);
        float2 p2 = unpk(acc[i][2]), p3 = unpk(acc[i][3]);
        *(float4*)(out0 + base)     = make_float4(p0.x, p0.y, p1.x, p1.y);
        *(float4*)(out0 + base + 4) = make_float4(p2.x, p2.y, p3.x, p3.y);
    }
}

// ============================================================================
extern "C" void kernel_launch(void* const* d_in, const int* in_sizes, int n_in,
                              void* d_out, int out_size) {
    const float* inp = (const float*)d_in[0];   // input
    const float* ctx = (const float*)d_in[1];   // context
    const float* W   = (const float*)d_in[2];   // W [8192,256]
    float* out = (float*)d_out;

    const int SMEM3 = (8192 + 16 * RSW) * 4;    // 49,408 B
    cudaFuncSetAttribute(k3_gemm_out, cudaFuncAttributeMaxDynamicSharedMemorySize, SMEM3);

    k1_gemm_T2<<<dim3(4 * KSPLIT, B_SZ), 128>>>(inp, W);
    k2_attn<<<B_SZ * 4, 256>>>(ctx, out + WC_ELEMS);
    k3_gemm_out<<<dim3(64, B_SZ), 128, SMEM3>>>(W, out);
}